// round 9
// baseline (speedup 1.0000x reference)
#include <cuda_runtime.h>
#include <cstdint>

// Problem constants (fixed by the dataset: V=8192 vertices, E=40000 tets)
#define V 8192
#define E 40000
#define E_BLOCKS ((E + 255) / 256)
#define ROWS_PER_BLOCK 8
#define MV_BLOCKS (V / ROWS_PER_BLOCK)   // 1024

// Scratch (device globals — no allocations allowed). 16B-aligned for float4 LDG.
__device__ __align__(16) float g_dx[V];
__device__ __align__(16) float g_dy[V];
__device__ __align__(16) float g_dz[V];
__device__ double g_kin_accum;    // sum_i delta_i . (M delta)_i   (atomic)
__device__ double g_el_accum;     // sum_e psi_e * measure_e       (atomic)
__device__ unsigned int g_ticket; // matvec completion counter

// ---------------------------------------------------------------------------
// Kernel 1 (fused prologue): elastic energy per element + delta computation.
//   threads with global id < V also compute
//     delta = next_position - (position + velocity*dt + ext_acc*dt^2)  (SoA)
//   elastic:
//     F[t][l] = sum_f next_pos[elem[e][f]][t] * poly[e][f][l]   (l < 3)
//     Ic = ||F||_F^2 ; J = det F ; alpha = 0.75*mu/lam + 1
//     psi = mu/2(Ic-3) + lam/2(J-alpha)^2 - mu/2*log(relu(Ic+1)+1e-30)
// elements is int32 on device (JAX x64 disabled); clamped defensively.
// ---------------------------------------------------------------------------
__global__ __launch_bounds__(256) void prologue_kernel(
    const float* __restrict__ next_pos,
    const float* __restrict__ pos,
    const float* __restrict__ vel,
    const float* __restrict__ ext,
    const float* __restrict__ ts_ptr,
    const int* __restrict__ elems,
    const float* __restrict__ poly,
    const float* __restrict__ measure,
    const float* __restrict__ lam,
    const float* __restrict__ mu)
{
    int gid = blockIdx.x * blockDim.x + threadIdx.x;

    if (gid == 0) {
        g_kin_accum = 0.0;
        g_el_accum  = 0.0;
        g_ticket    = 0u;
    }

    // --- delta part (first V threads) ---
    if (gid < V) {
        float dt  = ts_ptr[0];
        float dt2 = dt * dt;
        int b = gid * 3;
        g_dx[gid] = next_pos[b + 0] - (pos[b + 0] + vel[b + 0] * dt + ext[b + 0] * dt2);
        g_dy[gid] = next_pos[b + 1] - (pos[b + 1] + vel[b + 1] * dt + ext[b + 1] * dt2);
        g_dz[gid] = next_pos[b + 2] - (pos[b + 2] + vel[b + 2] * dt + ext[b + 2] * dt2);
    }

    // --- elastic part ---
    float val = 0.f;
    if (gid < E) {
        int e = gid;
        float F00 = 0.f, F01 = 0.f, F02 = 0.f;
        float F10 = 0.f, F11 = 0.f, F12 = 0.f;
        float F20 = 0.f, F21 = 0.f, F22 = 0.f;
        const int4 ev = reinterpret_cast<const int4*>(elems)[e];
        int vidx[4] = { ev.x, ev.y, ev.z, ev.w };
        const float4* __restrict__ pl4 = reinterpret_cast<const float4*>(poly) + (size_t)e * 4;
#pragma unroll
        for (int f = 0; f < 4; ++f) {
            int vi = vidx[f];
            vi = vi < 0 ? 0 : (vi >= V ? V - 1 : vi);   // defensive clamp
            const float* p = next_pos + (size_t)vi * 3;
            float px = p[0], py = p[1], pz = p[2];
            float4 pl = pl4[f];
            float p0 = pl.x, p1 = pl.y, p2 = pl.z;
            F00 += px * p0; F01 += px * p1; F02 += px * p2;
            F10 += py * p0; F11 += py * p1; F12 += py * p2;
            F20 += pz * p0; F21 += pz * p1; F22 += pz * p2;
        }
        float Ic = F00*F00 + F01*F01 + F02*F02
                 + F10*F10 + F11*F11 + F12*F12
                 + F20*F20 + F21*F21 + F22*F22;
        float J = F00 * (F11 * F22 - F12 * F21)
                - F01 * (F10 * F22 - F12 * F20)
                + F02 * (F10 * F21 - F11 * F20);
        float l = lam[e], m = mu[e];
        float alpha = 0.75f * m / l + 1.0f;
        float Icv = fmaxf(Ic + 1.0f, 0.0f);
        float d = J - alpha;
        float psi = 0.5f * m * (Ic - 3.0f)
                  + 0.5f * l * d * d
                  - 0.5f * m * logf(Icv + 1e-30f);
        val = psi * measure[(size_t)e * 4 + 3];
    }

#pragma unroll
    for (int off = 16; off > 0; off >>= 1)
        val += __shfl_down_sync(0xFFFFFFFFu, val, off);
    __shared__ float sh[8];
    int lane = threadIdx.x & 31;
    int warp = threadIdx.x >> 5;
    if (lane == 0) sh[warp] = val;
    __syncthreads();
    if (threadIdx.x == 0) {
        float s = 0.f;
#pragma unroll
        for (int w = 0; w < 8; ++w) s += sh[w];
        atomicAdd(&g_el_accum, (double)s);
    }
}

// ---------------------------------------------------------------------------
// Kernel 2: matvec + dot, 8 rows per block. Each delta float4 load feeds
// 8 rows (24 independent FMA chains) -> deep front-batched M loads, delta L1
// traffic halved again vs 4-row blocks. M streamed with __ldcs (no reuse).
// Last block (ticket) writes the outputs.
// ---------------------------------------------------------------------------
__global__ __launch_bounds__(256) void matvec_kernel(const float* __restrict__ M,
                                                     const float* __restrict__ ts_ptr,
                                                     float* __restrict__ out)
{
    const int row0 = blockIdx.x * ROWS_PER_BLOCK;
    const float4* __restrict__ DX = reinterpret_cast<const float4*>(g_dx);
    const float4* __restrict__ DY = reinterpret_cast<const float4*>(g_dy);
    const float4* __restrict__ DZ = reinterpret_cast<const float4*>(g_dz);

    const float4* Mr[ROWS_PER_BLOCK];
#pragma unroll
    for (int r = 0; r < ROWS_PER_BLOCK; ++r)
        Mr[r] = reinterpret_cast<const float4*>(M + (size_t)(row0 + r) * V);

    // acc[r][c]: r = row-in-block, c = x/y/z
    float acc[ROWS_PER_BLOCK][3];
#pragma unroll
    for (int r = 0; r < ROWS_PER_BLOCK; ++r) {
        acc[r][0] = 0.f; acc[r][1] = 0.f; acc[r][2] = 0.f;
    }

#pragma unroll
    for (int it = 0; it < (V / 4) / 256; ++it) {
        int idx = threadIdx.x + it * 256;
        float4 x = DX[idx];
        float4 y = DY[idx];
        float4 z = DZ[idx];
        float4 m[ROWS_PER_BLOCK];
#pragma unroll
        for (int r = 0; r < ROWS_PER_BLOCK; ++r)
            m[r] = __ldcs(&Mr[r][idx]);
#pragma unroll
        for (int r = 0; r < ROWS_PER_BLOCK; ++r) {
            acc[r][0] += m[r].x*x.x + m[r].y*x.y + m[r].z*x.z + m[r].w*x.w;
            acc[r][1] += m[r].x*y.x + m[r].y*y.y + m[r].z*y.z + m[r].w*y.w;
            acc[r][2] += m[r].x*z.x + m[r].y*z.y + m[r].z*z.z + m[r].w*z.w;
        }
    }

    // reduce 24 partials: warp shuffles then smem
#pragma unroll
    for (int off = 16; off > 0; off >>= 1) {
#pragma unroll
        for (int r = 0; r < ROWS_PER_BLOCK; ++r) {
            acc[r][0] += __shfl_down_sync(0xFFFFFFFFu, acc[r][0], off);
            acc[r][1] += __shfl_down_sync(0xFFFFFFFFu, acc[r][1], off);
            acc[r][2] += __shfl_down_sync(0xFFFFFFFFu, acc[r][2], off);
        }
    }
    __shared__ float sh[ROWS_PER_BLOCK * 3][8];
    int lane = threadIdx.x & 31;
    int warp = threadIdx.x >> 5;
    if (lane == 0) {
#pragma unroll
        for (int r = 0; r < ROWS_PER_BLOCK; ++r) {
            sh[r*3+0][warp] = acc[r][0];
            sh[r*3+1][warp] = acc[r][1];
            sh[r*3+2][warp] = acc[r][2];
        }
    }
    __syncthreads();

    if (threadIdx.x < ROWS_PER_BLOCK * 3) {
        float s = 0.f;
#pragma unroll
        for (int w = 0; w < 8; ++w) s += sh[threadIdx.x][w];
        sh[threadIdx.x][0] = s;
    }
    __syncthreads();

    if (threadIdx.x == 0) {
        double contrib = 0.0;
#pragma unroll
        for (int r = 0; r < ROWS_PER_BLOCK; ++r) {
            int row = row0 + r;
            contrib += (double)g_dx[row] * sh[r*3+0][0]
                     + (double)g_dy[row] * sh[r*3+1][0]
                     + (double)g_dz[row] * sh[r*3+2][0];
        }
        atomicAdd(&g_kin_accum, contrib);

        __threadfence();
        unsigned int t = atomicAdd(&g_ticket, 1u);
        if (t == (unsigned int)(MV_BLOCKS - 1)) {
            // all kinetic atomics visible; elastic finished (stream order)
            double dt = (double)ts_ptr[0];
            double inv_h = 1.0 / dt;
            double coeff = inv_h * inv_h * 0.5;
            double kin = coeff * g_kin_accum;
            double el  = g_el_accum;
            out[0] = (float)(kin + el);
            out[1] = (float)kin;
            out[2] = (float)el;
        }
    }
}

// ---------------------------------------------------------------------------
// Launch
// ---------------------------------------------------------------------------
extern "C" void kernel_launch(void* const* d_in, const int* in_sizes, int n_in,
                              void* d_out, int out_size)
{
    const float* next_pos = (const float*)d_in[0];
    const float* pos      = (const float*)d_in[1];
    const float* vel      = (const float*)d_in[2];
    const float* ext      = (const float*)d_in[3];
    const float* M        = (const float*)d_in[4];
    const int*   elems    = (const int*)d_in[5];
    const float* poly     = (const float*)d_in[6];
    const float* measure  = (const float*)d_in[7];
    const float* lam      = (const float*)d_in[8];
    const float* mu       = (const float*)d_in[9];
    const float* ts       = (const float*)d_in[10];
    float* out = (float*)d_out;

    prologue_kernel<<<E_BLOCKS, 256>>>(next_pos, pos, vel, ext, ts,
                                       elems, poly, measure, lam, mu);
    matvec_kernel<<<MV_BLOCKS, 256>>>(M, ts, out);
}